// round 14
// baseline (speedup 1.0000x reference)
#include <cuda_runtime.h>
#include <cuda_bf16.h>

// Output[b,s,:] == mean(knowledge, axis=0) for every (b,s):
// top_k with max_chunks == K selects a permutation of ALL knowledge rows,
// so mean(take(knowledge, top_k), axis=1) == mean(knowledge, axis=0).
//
// Final probe: intersection of all measured winners. Warp-autonomous
// (zero smem / zero barriers, from R13) at the R9 grid point: 256 CTAs
// x 256 threads. Each CTA = one 64-float4 column half x 32 rows; 8 warps
// own 8 float4 cols each; per thread 16 front-batched loads, 2 shfl_xor,
// 8 branch-free coalesced STG.128. Cheapest critical path of any round.

#define E_DIM 512
#define K_ROWS 64
#define THREADS 256
#define COLS4 (E_DIM / 4)       // 128 float4 per full row
#define NCB 2                   // column halves
#define CB4 (COLS4 / NCB)       // 64 float4 columns per half
#define ROWS_PER_CTA 32         // 128 row-blocks x 2 col-halves = 256 CTAs

__global__ void __launch_bounds__(THREADS)
fused_mean_broadcast(const float4* __restrict__ knowledge4,
                     float4* __restrict__ out) {
    int t = threadIdx.x;
    int lane = t & 31;
    int w = t >> 5;             // warp 0..7: owns float4 cols [8w, 8w+8) of the half
    int c = lane & 7;           // column within warp slice
    int g = lane >> 3;          // row-group 0..3: rows [16g, 16g+16)

    int cb = blockIdx.x & (NCB - 1);   // column half 0..1
    int rb = blockIdx.x >> 1;          // row block 0..127
    int col = cb * CB4 + w * 8 + c;    // global float4 column

    // 16 independent front-batched loads (warp load = 8 full 128B sectors).
    float4 s = make_float4(0.f, 0.f, 0.f, 0.f);
#pragma unroll
    for (int k = 0; k < K_ROWS / 4; ++k) {
        float4 a = knowledge4[(g * (K_ROWS / 4) + k) * COLS4 + col];
        s.x += a.x; s.y += a.y; s.z += a.z; s.w += a.w;
    }

    // Lanes with equal c differ only in the g bits (3,4): two xor
    // shuffles complete the 64-row column sum. No smem, no barrier.
#pragma unroll
    for (int d = 8; d <= 16; d <<= 1) {
        s.x += __shfl_xor_sync(0xffffffffu, s.x, d);
        s.y += __shfl_xor_sync(0xffffffffu, s.y, d);
        s.z += __shfl_xor_sync(0xffffffffu, s.z, d);
        s.w += __shfl_xor_sync(0xffffffffu, s.w, d);
    }
    const float inv = 1.0f / (float)K_ROWS;
    s.x *= inv; s.y *= inv; s.z *= inv; s.w *= inv;

    // CTA writes rows [rb*32, +32) of its column half; replica-group g
    // writes 8 rows. Warp store = 4 x 128B sectors, branch-free.
    int r0 = rb * ROWS_PER_CTA + g * (ROWS_PER_CTA / 4);
    size_t base = (size_t)r0 * COLS4 + col;
#pragma unroll
    for (int r = 0; r < ROWS_PER_CTA / 4; ++r) {
        out[base + (size_t)r * COLS4] = s;
    }
}

extern "C" void kernel_launch(void* const* d_in, const int* in_sizes, int n_in,
                              void* d_out, int out_size) {
    // d_in[0]: query_embedding [4,1024,512] f32 (unused — output is query-independent)
    // d_in[1]: knowledge [64,512] f32
    const float* knowledge = (const float*)d_in[1];
    float* out = (float*)d_out;

    int rows = out_size / E_DIM;                 // 4096
    int blocks = NCB * (rows / ROWS_PER_CTA);    // 256

    fused_mean_broadcast<<<blocks, THREADS>>>(
        reinterpret_cast<const float4*>(knowledge),
        reinterpret_cast<float4*>(out));
}